// round 2
// baseline (speedup 1.0000x reference)
#include <cuda_runtime.h>
#include <math.h>

#define Bc 4
#define Sc 1024
#define Dc 768
#define Nc 12
#define Hc 64
#define Rc 2048
#define SCALE 0.125f
#define INFV 1000000.0f
#define EPSV 1e-9f

typedef unsigned long long ull;

// ---------------- packed f32x2 helpers (sm_100a FFMA2 path) ----------------
__device__ __forceinline__ void fma2(ull& d, ull a, ull b) {
    asm("fma.rn.f32x2 %0, %1, %2, %0;" : "+l"(d) : "l"(a), "l"(b));
}
__device__ __forceinline__ void mul2(ull& d, ull a) {
    asm("mul.rn.f32x2 %0, %0, %1;" : "+l"(d) : "l"(a));
}
__device__ __forceinline__ ull pack2(float x) {
    ull r; asm("mov.b64 %0, {%1, %1};" : "=l"(r) : "f"(x)); return r;
}
__device__ __forceinline__ float sum2(ull v) {
    float lo, hi; asm("mov.b64 {%0, %1}, %2;" : "=f"(lo), "=f"(hi) : "l"(v));
    return lo + hi;
}
__device__ __forceinline__ ull ld2(const float* p) {
    return *reinterpret_cast<const ull*>(p);
}

// ---------------- scratch ----------------
__device__ float g_qh[Bc*Nc*Sc*Hc];
__device__ float g_kh[Bc*Nc*Sc*Hc];
__device__ float g_vh[Bc*Nc*Sc*Hc];
__device__ float g_rh[Nc*Rc*Hc];
__device__ float g_tt[Bc*Nc*Sc*2];
__device__ float g_av[Bc*Nc*Sc*Hc];
__device__ float g_x [Bc*Sc*Dc];

// ---------------- projection GEMM (128x128 tile, 8x8/thread, f32x2) ----------
__global__ __launch_bounds__(256, 2)
void gemm_proj2(const float* __restrict__ A, const float* __restrict__ W,
                const float* __restrict__ bias, float scale,
                int Srows, float* __restrict__ out) {
    __shared__ float As[16*129];
    __shared__ float Ws[16*132];
    int tid = threadIdx.x, tx = tid & 15, ty = tid >> 4;
    int m0 = blockIdx.y * 128, n0 = blockIdx.x * 128;
    ull acc2[8][4];
    #pragma unroll
    for (int i = 0; i < 8; i++)
        #pragma unroll
        for (int j = 0; j < 4; j++) acc2[i][j] = 0ull;

    for (int k0 = 0; k0 < Dc; k0 += 16) {
        #pragma unroll
        for (int p = 0; p < 2; p++) {
            int lin = tid + p * 256;
            int m = lin >> 2, kq = (lin & 3) * 4;
            float4 v = *(const float4*)(A + (size_t)(m0 + m) * Dc + k0 + kq);
            As[(kq+0)*129 + m] = v.x; As[(kq+1)*129 + m] = v.y;
            As[(kq+2)*129 + m] = v.z; As[(kq+3)*129 + m] = v.w;
            int k = lin >> 5, nq = lin & 31;
            *(float4*)(Ws + k*132 + nq*4) =
                *(const float4*)(W + (size_t)(k0 + k) * Dc + n0 + nq*4);
        }
        __syncthreads();
        #pragma unroll
        for (int k = 0; k < 16; k++) {
            ull a2[8], w2[4];
            #pragma unroll
            for (int i = 0; i < 8; i++) a2[i] = pack2(As[k*129 + ty + i*16]);
            #pragma unroll
            for (int jp = 0; jp < 4; jp++) w2[jp] = ld2(Ws + k*132 + tx*2 + jp*32);
            #pragma unroll
            for (int i = 0; i < 8; i++)
                #pragma unroll
                for (int jp = 0; jp < 4; jp++) fma2(acc2[i][jp], a2[i], w2[jp]);
        }
        __syncthreads();
    }
    #pragma unroll
    for (int i = 0; i < 8; i++) {
        int row = m0 + ty + i*16;
        int bb = row / Srows, ss = row % Srows;
        #pragma unroll
        for (int jp = 0; jp < 4; jp++) {
            float lo, hi;
            asm("mov.b64 {%0, %1}, %2;" : "=f"(lo), "=f"(hi) : "l"(acc2[i][jp]));
            int col0 = n0 + tx*2 + jp*32;
            #pragma unroll
            for (int e = 0; e < 2; e++) {
                int col = col0 + e;
                float v = (e ? hi : lo) * scale;
                if (bias) v += bias[col];
                out[(((size_t)bb*Nc + (col >> 6))*Srows + ss)*Hc + (col & 63)] = v;
            }
        }
    }
}

// ---------------- output GEMM + residual (reads g_av gathered) ---------------
__global__ __launch_bounds__(256, 2)
void gemm_out2(const float* __restrict__ Wo, const float* __restrict__ bo,
               const float* __restrict__ query) {
    __shared__ float As[16*129];
    __shared__ float Ws[16*132];
    int tid = threadIdx.x, tx = tid & 15, ty = tid >> 4;
    int m0 = blockIdx.y * 128, n0 = blockIdx.x * 128;
    ull acc2[8][4];
    #pragma unroll
    for (int i = 0; i < 8; i++)
        #pragma unroll
        for (int j = 0; j < 4; j++) acc2[i][j] = 0ull;

    for (int k0 = 0; k0 < Dc; k0 += 16) {
        #pragma unroll
        for (int p = 0; p < 2; p++) {
            int lin = tid + p * 256;
            int m = lin >> 2, kq = (lin & 3) * 4;
            int row = m0 + m, colk = k0 + kq;
            float4 v = *(const float4*)(g_av +
                (((size_t)(row >> 10)*Nc + (colk >> 6))*Sc + (row & 1023))*Hc + (colk & 63));
            As[(kq+0)*129 + m] = v.x; As[(kq+1)*129 + m] = v.y;
            As[(kq+2)*129 + m] = v.z; As[(kq+3)*129 + m] = v.w;
            int k = lin >> 5, nq = lin & 31;
            *(float4*)(Ws + k*132 + nq*4) =
                *(const float4*)(Wo + (size_t)(k0 + k) * Dc + n0 + nq*4);
        }
        __syncthreads();
        #pragma unroll
        for (int k = 0; k < 16; k++) {
            ull a2[8], w2[4];
            #pragma unroll
            for (int i = 0; i < 8; i++) a2[i] = pack2(As[k*129 + ty + i*16]);
            #pragma unroll
            for (int jp = 0; jp < 4; jp++) w2[jp] = ld2(Ws + k*132 + tx*2 + jp*32);
            #pragma unroll
            for (int i = 0; i < 8; i++)
                #pragma unroll
                for (int jp = 0; jp < 4; jp++) fma2(acc2[i][jp], a2[i], w2[jp]);
        }
        __syncthreads();
    }
    #pragma unroll
    for (int i = 0; i < 8; i++) {
        int row = m0 + ty + i*16;
        #pragma unroll
        for (int jp = 0; jp < 4; jp++) {
            float lo, hi;
            asm("mov.b64 {%0, %1}, %2;" : "=f"(lo), "=f"(hi) : "l"(acc2[i][jp]));
            int col0 = n0 + tx*2 + jp*32;
            #pragma unroll
            for (int e = 0; e < 2; e++) {
                int col = col0 + e;
                g_x[(size_t)row*Dc + col] = (e ? hi : lo) + bo[col]
                                            + query[(size_t)row*Dc + col];
            }
        }
    }
}

// ---------------- token-type bias ----------------
__global__ __launch_bounds__(256)
void tt_kernel(const float* __restrict__ rsb, const float* __restrict__ seg) {
    int warp = threadIdx.x >> 5, lane = threadIdx.x & 31;
    int row = blockIdx.x * 8 + warp;
    int n = (row / Sc) % Nc;
    const float* q = &g_qh[(size_t)row * Hc];
    float d = 0.f, s = 0.f;
    #pragma unroll
    for (int p = 0; p < 2; p++) {
        int h = lane + p*32;
        float qv = q[h] + rsb[n*Hc + h] * SCALE;
        d += qv * seg[(0*Nc + n)*Hc + h];
        s += qv * seg[(1*Nc + n)*Hc + h];
    }
    #pragma unroll
    for (int off = 16; off; off >>= 1) {
        d += __shfl_xor_sync(~0u, d, off);
        s += __shfl_xor_sync(~0u, s, off);
    }
    if (lane == 0) { g_tt[(size_t)row*2 + 0] = d; g_tt[(size_t)row*2 + 1] = s; }
}

// ---------------- fused attention (f32x2 packed over h/j parity) -------------
extern __shared__ float sm[];
__global__ __launch_bounds__(256)
void attn_kernel(const float* __restrict__ rwb, const float* __restrict__ rrb,
                 const unsigned char* __restrict__ ttm,
                 const float* __restrict__ amask_g,
                 const float* __restrict__ clsm) {
    float* qw    = sm;                 // 64*66  [i][h]
    float* qr    = qw + 64*66;         // 64*66  [i][h]
    float* kv    = qr + 64*66;         // 64*66  K:[j][h] then V:[h][j]
    float* ps    = kv + 64*66;         // 64*66  [i][j]
    float* rs    = ps + 64*66;         // 128*66 [u][h]
    float* amask = rs + 128*66;        // 64
    float* ttd   = amask + 64;         // 128

    int i0 = blockIdx.x * 64;
    int n  = blockIdx.y, b = blockIdx.z;
    int tid = threadIdx.x;
    int tx = tid & 15, ty = tid >> 4;
    int tx4 = tx*4, ty4 = ty*4;

    const float* qbase = &g_qh[(((size_t)b*Nc + n)*Sc + i0) * Hc];
    const float* kbase = &g_kh[(((size_t)b*Nc + n)*Sc) * Hc];
    const float* vbase = &g_vh[(((size_t)b*Nc + n)*Sc) * Hc];
    const float* rbase = &g_rh[(size_t)n * Rc * Hc];

    for (int idx = tid; idx < 64*32; idx += 256) {
        int r = idx >> 5, h2 = (idx & 31) * 2;
        float2 v  = *(const float2*)(qbase + r*Hc + h2);
        float2 w  = *(const float2*)(rwb + n*Hc + h2);
        float2 rr = *(const float2*)(rrb + n*Hc + h2);
        qw[r*66 + h2]   = v.x + w.x  * SCALE;
        qw[r*66 + h2+1] = v.y + w.y  * SCALE;
        qr[r*66 + h2]   = v.x + rr.x * SCALE;
        qr[r*66 + h2+1] = v.y + rr.y * SCALE;
    }
    for (int idx = tid; idx < 128; idx += 256)
        ttd[idx] = g_tt[(((size_t)b*Nc + n)*Sc + i0)*2 + idx];

    ull o2[4][4];
    float m_[4], l_[4];
    #pragma unroll
    for (int a = 0; a < 4; a++) {
        m_[a] = -3.0e38f; l_[a] = 0.f;
        #pragma unroll
        for (int c = 0; c < 4; c++) o2[a][c] = 0ull;
    }

    int ibase = 60 + 4*(tx - ty);

    for (int j0 = 0; j0 < Sc; j0 += 64) {
        __syncthreads();
        for (int idx = tid; idx < 64*32; idx += 256) {
            int r = idx >> 5, h2 = (idx & 31) * 2;
            *(float2*)(kv + r*66 + h2) =
                *(const float2*)(kbase + (size_t)(j0 + r)*Hc + h2);
        }
        int t_base = Sc - i0 - 63 + j0;
        for (int idx = tid; idx < 127*32; idx += 256) {
            int r = idx >> 5, h2 = (idx & 31) * 2;
            int t = t_base + r;
            float2 v = (t >= 0 && t < Rc)
                     ? *(const float2*)(rbase + (size_t)t*Hc + h2)
                     : make_float2(0.f, 0.f);
            *(float2*)(rs + r*66 + h2) = v;
        }
        if (tid < 64) amask[tid] = amask_g[b*Sc + j0 + tid];
        __syncthreads();

        ull sc2[4][4], pp2[4][4];
        #pragma unroll
        for (int a = 0; a < 4; a++)
            #pragma unroll
            for (int c = 0; c < 4; c++) { sc2[a][c] = 0ull; pp2[a][c] = 0ull; }

        #pragma unroll 2
        for (int h2 = 0; h2 < 64; h2 += 2) {
            ull qa2[4], ra2[4], kb2[4], rv2[7];
            #pragma unroll
            for (int a = 0; a < 4; a++) {
                qa2[a] = ld2(qw + (ty4 + a)*66 + h2);
                ra2[a] = ld2(qr + (ty4 + a)*66 + h2);
            }
            #pragma unroll
            for (int c = 0; c < 4; c++) kb2[c] = ld2(kv + (tx4 + c)*66 + h2);
            #pragma unroll
            for (int d = 0; d < 7; d++) rv2[d] = ld2(rs + (ibase + d)*66 + h2);
            #pragma unroll
            for (int a = 0; a < 4; a++)
                #pragma unroll
                for (int c = 0; c < 4; c++) {
                    fma2(sc2[a][c], qa2[a], kb2[c]);
                    fma2(pp2[a][c], ra2[a], rv2[c - a + 3]);
                }
        }

        #pragma unroll
        for (int a = 0; a < 4; a++) {
            int ii = i0 + ty4 + a;
            float tt_d = ttd[(ty4 + a)*2 + 0];
            float tt_s = ttd[(ty4 + a)*2 + 1];
            float p[4];
            float mrow = -3.0e38f;
            #pragma unroll
            for (int c = 0; c < 4; c++) {
                int jj = j0 + tx4 + c;
                float cls = clsm[(size_t)ii*Sc + jj];
                float ttv = ttm[((size_t)b*Sc + ii)*Sc + jj] ? tt_s : tt_d;
                float scv = sum2(sc2[a][c]) + cls*(sum2(pp2[a][c]) + ttv)
                            - INFV*(1.f - amask[tx4 + c]);
                p[c] = scv;
                mrow = fmaxf(mrow, scv);
            }
            #pragma unroll
            for (int off = 8; off; off >>= 1)
                mrow = fmaxf(mrow, __shfl_xor_sync(~0u, mrow, off, 16));
            float mn = fmaxf(m_[a], mrow);
            float corr = __expf(m_[a] - mn);
            float lsum = 0.f;
            #pragma unroll
            for (int c = 0; c < 4; c++) { p[c] = __expf(p[c] - mn); lsum += p[c]; }
            #pragma unroll
            for (int off = 8; off; off >>= 1)
                lsum += __shfl_xor_sync(~0u, lsum, off, 16);
            l_[a] = l_[a]*corr + lsum;
            m_[a] = mn;
            ull corr2 = pack2(corr);
            #pragma unroll
            for (int c = 0; c < 4; c++) mul2(o2[a][c], corr2);
            #pragma unroll
            for (int c = 0; c < 4; c++) ps[(ty4 + a)*66 + tx4 + c] = p[c];
        }
        __syncthreads();
        // V transposed into kv: [h][j]
        for (int idx = tid; idx < 64*32; idx += 256) {
            int j = idx >> 5, h2 = (idx & 31) * 2;
            float2 v = *(const float2*)(vbase + (size_t)(j0 + j)*Hc + h2);
            kv[(h2  )*66 + j] = v.x;
            kv[(h2+1)*66 + j] = v.y;
        }
        __syncthreads();

        #pragma unroll 2
        for (int j2 = 0; j2 < 64; j2 += 2) {
            ull p2[4], v2[4];
            #pragma unroll
            for (int a = 0; a < 4; a++) p2[a] = ld2(ps + (ty4 + a)*66 + j2);
            #pragma unroll
            for (int c = 0; c < 4; c++) v2[c] = ld2(kv + (tx4 + c)*66 + j2);
            #pragma unroll
            for (int a = 0; a < 4; a++)
                #pragma unroll
                for (int c = 0; c < 4; c++) fma2(o2[a][c], p2[a], v2[c]);
        }
    }

    float* outb = &g_av[(((size_t)b*Nc + n)*Sc + i0) * Hc];
    #pragma unroll
    for (int a = 0; a < 4; a++) {
        float inv = 1.f / l_[a];
        #pragma unroll
        for (int c = 0; c < 4; c++)
            outb[(ty4 + a)*Hc + tx4 + c] = sum2(o2[a][c]) * inv;
    }
}

// ---------------- LayerNorm ----------------
__global__ __launch_bounds__(256)
void ln_kernel(const float* __restrict__ lng, const float* __restrict__ lnb,
               float* __restrict__ out) {
    __shared__ float red[8];
    __shared__ float stat;
    int row = blockIdx.x;
    const float* x = &g_x[(size_t)row * Dc];
    int t = threadIdx.x;
    float v[3];
    float s = 0.f;
    #pragma unroll
    for (int p = 0; p < 3; p++) { v[p] = x[t + p*256]; s += v[p]; }
    #pragma unroll
    for (int off = 16; off; off >>= 1) s += __shfl_xor_sync(~0u, s, off);
    if ((t & 31) == 0) red[t >> 5] = s;
    __syncthreads();
    if (t < 32) {
        float r = (t < 8) ? red[t] : 0.f;
        #pragma unroll
        for (int off = 4; off; off >>= 1) r += __shfl_xor_sync(~0u, r, off);
        if (t == 0) stat = r * (1.f / Dc);
    }
    __syncthreads();
    float mu = stat;
    float s2 = 0.f;
    #pragma unroll
    for (int p = 0; p < 3; p++) { float d = v[p] - mu; s2 += d*d; }
    #pragma unroll
    for (int off = 16; off; off >>= 1) s2 += __shfl_xor_sync(~0u, s2, off);
    if ((t & 31) == 0) red[t >> 5] = s2;
    __syncthreads();
    if (t < 32) {
        float r = (t < 8) ? red[t] : 0.f;
        #pragma unroll
        for (int off = 4; off; off >>= 1) r += __shfl_xor_sync(~0u, r, off);
        if (t == 0) stat = rsqrtf(r * (1.f / Dc) + EPSV);
    }
    __syncthreads();
    float rstd = stat;
    #pragma unroll
    for (int p = 0; p < 3; p++) {
        int i = t + p*256;
        out[(size_t)row*Dc + i] = (v[p] - mu) * rstd * lng[i] + lnb[i];
    }
}

// ---------------- launch ----------------
extern "C" void kernel_launch(void* const* d_in, const int* in_sizes, int n_in,
                              void* d_out, int out_size) {
    const float* query = (const float*)d_in[0];
    const float* key   = (const float*)d_in[1];
    const float* value = (const float*)d_in[2];
    const float* pose  = (const float*)d_in[3];
    const unsigned char* ttm = (const unsigned char*)d_in[4];
    const float* amask = (const float*)d_in[5];
    const float* clsm  = (const float*)d_in[6];
    const float* Wq    = (const float*)d_in[7];
    const float* Wk    = (const float*)d_in[8];
    const float* bk    = (const float*)d_in[9];
    const float* Wv    = (const float*)d_in[10];
    const float* bv    = (const float*)d_in[11];
    const float* rwb   = (const float*)d_in[12];
    const float* rrb   = (const float*)d_in[13];
    const float* rker  = (const float*)d_in[14];
    const float* rsb   = (const float*)d_in[15];
    const float* seg   = (const float*)d_in[16];
    const float* Wo    = (const float*)d_in[17];
    const float* bo    = (const float*)d_in[18];
    const float* lng   = (const float*)d_in[19];
    const float* lnb   = (const float*)d_in[20];
    float* out = (float*)d_out;

    float *qh, *kh, *vh, *rh;
    cudaGetSymbolAddress((void**)&qh, g_qh);
    cudaGetSymbolAddress((void**)&kh, g_kh);
    cudaGetSymbolAddress((void**)&vh, g_vh);
    cudaGetSymbolAddress((void**)&rh, g_rh);

    dim3 blk(256);
    gemm_proj2<<<dim3(6, 32), blk>>>(query, Wq, nullptr, SCALE, Sc, qh);
    gemm_proj2<<<dim3(6, 32), blk>>>(key,   Wk, bk,      1.0f,  Sc, kh);
    gemm_proj2<<<dim3(6, 32), blk>>>(value, Wv, bv,      1.0f,  Sc, vh);
    gemm_proj2<<<dim3(6, 16), blk>>>(pose,  rker, nullptr, 1.0f, Rc, rh);

    tt_kernel<<<Bc*Nc*Sc/8, blk>>>(rsb, seg);

    size_t smem = (size_t)(4*64*66 + 128*66 + 64 + 128) * sizeof(float); // 102,144 B
    cudaFuncSetAttribute(attn_kernel, cudaFuncAttributeMaxDynamicSharedMemorySize,
                         (int)smem);
    attn_kernel<<<dim3(Sc/64, Nc, Bc), blk, smem>>>(rwb, rrb, ttm, amask, clsm);

    gemm_out2<<<dim3(6, 32), blk>>>(Wo, bo, query);

    ln_kernel<<<Bc*Sc, blk>>>(lng, lnb, out);
}

// round 3
// speedup vs baseline: 3.6832x; 3.6832x over previous
#include <cuda_runtime.h>
#include <math.h>

#define Bc 4
#define Sc 1024
#define Dc 768
#define Nc 12
#define Hc 64
#define Rc 2048
#define SCALE 0.125f
#define INFV 1000000.0f
#define EPSV 1e-9f

// ---------------- tf32 helpers ----------------
__device__ __forceinline__ unsigned f2tf(float x) {
    unsigned u; asm("cvt.rna.tf32.f32 %0, %1;" : "=r"(u) : "f"(x)); return u;
}
__device__ __forceinline__ float4 cvt4(float4 v) {
    v.x = __uint_as_float(f2tf(v.x)); v.y = __uint_as_float(f2tf(v.y));
    v.z = __uint_as_float(f2tf(v.z)); v.w = __uint_as_float(f2tf(v.w));
    return v;
}
// m16n8k8 tf32 mma: A row-major frag a0..a3, B col-frag b0,b1, C +=.
__device__ __forceinline__ void mma8(float4& c, unsigned a0, unsigned a1,
                                     unsigned a2, unsigned a3,
                                     unsigned b0, unsigned b1) {
    asm volatile(
        "mma.sync.aligned.m16n8k8.row.col.f32.tf32.tf32.f32 "
        "{%0,%1,%2,%3}, {%4,%5,%6,%7}, {%8,%9}, {%0,%1,%2,%3};"
        : "+f"(c.x), "+f"(c.y), "+f"(c.z), "+f"(c.w)
        : "r"(a0), "r"(a1), "r"(a2), "r"(a3), "r"(b0), "r"(b1));
}

// ---------------- scratch ----------------
__device__ float g_qh[Bc*Nc*Sc*Hc];   // tf32-rounded
__device__ float g_kh[Bc*Nc*Sc*Hc];   // tf32-rounded
__device__ float g_vh[Bc*Nc*Sc*Hc];   // tf32-rounded
__device__ float g_rh[Nc*Rc*Hc];      // tf32-rounded
__device__ float g_tt[Bc*Nc*Sc*2];
__device__ float g_av[Bc*Nc*Sc*Hc];   // tf32-rounded
__device__ float g_x [Bc*Sc*Dc];

// ============ projection GEMM: out = cvt_tf32(A@W * scale + bias), scattered ============
// Block: 256 thr, tile 128(M) x 64(N), KC=32. Warp tile 32x32.
__global__ __launch_bounds__(256)
void gemm_proj_t(const float* __restrict__ A, const float* __restrict__ W,
                 const float* __restrict__ bias, float scale, int sshift,
                 float* __restrict__ out) {
    __shared__ float As[128*36];
    __shared__ float Ws[32*72];
    int tid = threadIdx.x, w = tid >> 5, lane = tid & 31;
    int g = lane >> 2, t = lane & 3;
    int wm = w & 3, wn = w >> 2;
    int m0 = blockIdx.y * 128, n0 = blockIdx.x * 64;
    int Srows = 1 << sshift;

    float4 c[2][4];
    #pragma unroll
    for (int mt = 0; mt < 2; mt++)
        #pragma unroll
        for (int nt = 0; nt < 4; nt++) c[mt][nt] = make_float4(0.f,0.f,0.f,0.f);

    for (int k0 = 0; k0 < Dc; k0 += 32) {
        #pragma unroll
        for (int p = 0; p < 4; p++) {
            int idx = tid + p*256;
            int m = idx >> 3, kq = (idx & 7) * 4;
            float4 v = *(const float4*)(A + (size_t)(m0+m)*Dc + k0 + kq);
            *(float4*)(As + m*36 + kq) = cvt4(v);
        }
        #pragma unroll
        for (int p = 0; p < 2; p++) {
            int idx = tid + p*256;
            int k = idx >> 4, nq = (idx & 15) * 4;
            float4 v = *(const float4*)(W + (size_t)(k0+k)*Dc + n0 + nq);
            *(float4*)(Ws + k*72 + nq) = cvt4(v);
        }
        __syncthreads();
        #pragma unroll
        for (int ks = 0; ks < 4; ks++) {
            int kb = ks * 8;
            unsigned a[2][4];
            #pragma unroll
            for (int mt = 0; mt < 2; mt++) {
                int bm = wm*32 + mt*16;
                a[mt][0] = __float_as_uint(As[(bm+g  )*36 + kb+t  ]);
                a[mt][1] = __float_as_uint(As[(bm+g+8)*36 + kb+t  ]);
                a[mt][2] = __float_as_uint(As[(bm+g  )*36 + kb+t+4]);
                a[mt][3] = __float_as_uint(As[(bm+g+8)*36 + kb+t+4]);
            }
            unsigned bb[4][2];
            #pragma unroll
            for (int nt = 0; nt < 4; nt++) {
                int bn = wn*32 + nt*8 + g;
                bb[nt][0] = __float_as_uint(Ws[(kb+t  )*72 + bn]);
                bb[nt][1] = __float_as_uint(Ws[(kb+t+4)*72 + bn]);
            }
            #pragma unroll
            for (int mt = 0; mt < 2; mt++)
                #pragma unroll
                for (int nt = 0; nt < 4; nt++)
                    mma8(c[mt][nt], a[mt][0],a[mt][1],a[mt][2],a[mt][3],
                         bb[nt][0], bb[nt][1]);
        }
        __syncthreads();
    }
    #pragma unroll
    for (int mt = 0; mt < 2; mt++) {
        #pragma unroll
        for (int nt = 0; nt < 4; nt++) {
            int col = n0 + wn*32 + nt*8 + 2*t;
            float b0 = bias ? __ldg(bias + col) : 0.f;
            float b1 = bias ? __ldg(bias + col + 1) : 0.f;
            int nn = col >> 6, h = col & 63;
            #pragma unroll
            for (int r = 0; r < 2; r++) {
                int row = m0 + wm*32 + mt*16 + g + r*8;
                int bbx = row >> sshift, ss = row & (Srows - 1);
                float v0 = (r ? c[mt][nt].z : c[mt][nt].x) * scale + b0;
                float v1 = (r ? c[mt][nt].w : c[mt][nt].y) * scale + b1;
                float2 o = make_float2(__uint_as_float(f2tf(v0)),
                                       __uint_as_float(f2tf(v1)));
                *(float2*)(out + (((size_t)bbx*Nc + nn)*Srows + ss)*Hc + h) = o;
            }
        }
    }
}

// ============ output GEMM + residual: g_x = g_av@Wo + bo + query (fp32 out) ============
__global__ __launch_bounds__(256)
void gemm_out_t(const float* __restrict__ Wo, const float* __restrict__ bo,
                const float* __restrict__ query) {
    __shared__ float As[128*36];
    __shared__ float Ws[32*72];
    int tid = threadIdx.x, w = tid >> 5, lane = tid & 31;
    int g = lane >> 2, t = lane & 3;
    int wm = w & 3, wn = w >> 2;
    int m0 = blockIdx.y * 128, n0 = blockIdx.x * 64;

    float4 c[2][4];
    #pragma unroll
    for (int mt = 0; mt < 2; mt++)
        #pragma unroll
        for (int nt = 0; nt < 4; nt++) c[mt][nt] = make_float4(0.f,0.f,0.f,0.f);

    for (int k0 = 0; k0 < Dc; k0 += 32) {
        #pragma unroll
        for (int p = 0; p < 4; p++) {
            int idx = tid + p*256;
            int m = idx >> 3, kq = (idx & 7) * 4;
            int row = m0 + m, colk = k0 + kq;
            float4 v = *(const float4*)(g_av +
                (((size_t)(row >> 10)*Nc + (colk >> 6))*Sc + (row & 1023))*Hc + (colk & 63));
            *(float4*)(As + m*36 + kq) = v;   // already tf32-rounded
        }
        #pragma unroll
        for (int p = 0; p < 2; p++) {
            int idx = tid + p*256;
            int k = idx >> 4, nq = (idx & 15) * 4;
            float4 v = *(const float4*)(Wo + (size_t)(k0+k)*Dc + n0 + nq);
            *(float4*)(Ws + k*72 + nq) = cvt4(v);
        }
        __syncthreads();
        #pragma unroll
        for (int ks = 0; ks < 4; ks++) {
            int kb = ks * 8;
            unsigned a[2][4];
            #pragma unroll
            for (int mt = 0; mt < 2; mt++) {
                int bm = wm*32 + mt*16;
                a[mt][0] = __float_as_uint(As[(bm+g  )*36 + kb+t  ]);
                a[mt][1] = __float_as_uint(As[(bm+g+8)*36 + kb+t  ]);
                a[mt][2] = __float_as_uint(As[(bm+g  )*36 + kb+t+4]);
                a[mt][3] = __float_as_uint(As[(bm+g+8)*36 + kb+t+4]);
            }
            unsigned bb[4][2];
            #pragma unroll
            for (int nt = 0; nt < 4; nt++) {
                int bn = wn*32 + nt*8 + g;
                bb[nt][0] = __float_as_uint(Ws[(kb+t  )*72 + bn]);
                bb[nt][1] = __float_as_uint(Ws[(kb+t+4)*72 + bn]);
            }
            #pragma unroll
            for (int mt = 0; mt < 2; mt++)
                #pragma unroll
                for (int nt = 0; nt < 4; nt++)
                    mma8(c[mt][nt], a[mt][0],a[mt][1],a[mt][2],a[mt][3],
                         bb[nt][0], bb[nt][1]);
        }
        __syncthreads();
    }
    #pragma unroll
    for (int mt = 0; mt < 2; mt++) {
        #pragma unroll
        for (int nt = 0; nt < 4; nt++) {
            int col = n0 + wn*32 + nt*8 + 2*t;
            float b0 = __ldg(bo + col), b1 = __ldg(bo + col + 1);
            #pragma unroll
            for (int r = 0; r < 2; r++) {
                int row = m0 + wm*32 + mt*16 + g + r*8;
                float2 q = *(const float2*)(query + (size_t)row*Dc + col);
                float v0 = (r ? c[mt][nt].z : c[mt][nt].x) + b0 + q.x;
                float v1 = (r ? c[mt][nt].w : c[mt][nt].y) + b1 + q.y;
                *(float2*)(g_x + (size_t)row*Dc + col) = make_float2(v0, v1);
            }
        }
    }
}

// ---------------- token-type bias ----------------
__global__ __launch_bounds__(256)
void tt_kernel(const float* __restrict__ rsb, const float* __restrict__ seg) {
    int warp = threadIdx.x >> 5, lane = threadIdx.x & 31;
    int row = blockIdx.x * 8 + warp;
    int n = (row / Sc) % Nc;
    const float* q = &g_qh[(size_t)row * Hc];
    float d = 0.f, s = 0.f;
    #pragma unroll
    for (int p = 0; p < 2; p++) {
        int h = lane + p*32;
        float qv = q[h] + rsb[n*Hc + h] * SCALE;
        d += qv * seg[(0*Nc + n)*Hc + h];
        s += qv * seg[(1*Nc + n)*Hc + h];
    }
    #pragma unroll
    for (int off = 16; off; off >>= 1) {
        d += __shfl_xor_sync(~0u, d, off);
        s += __shfl_xor_sync(~0u, s, off);
    }
    if (lane == 0) { g_tt[(size_t)row*2 + 0] = d; g_tt[(size_t)row*2 + 1] = s; }
}

// ============ fused attention (tf32 mma) ============
#define LDQ 68
#define LDV 72
#define LDP 132
extern __shared__ float smdyn[];
__global__ __launch_bounds__(256, 2)
void attn_kernel(const float* __restrict__ rwb, const float* __restrict__ rrb,
                 const unsigned char* __restrict__ ttm,
                 const float* __restrict__ amask_g,
                 const float* __restrict__ clsm) {
    float* sq   = smdyn;            // 64*68 raw q (tf32-rounded, pre-bias)
    float* skv  = sq  + 64*LDQ;     // 64*72: K (stride 68) then V (stride 72)
    float* srs  = skv + 64*LDV;     // 128*68 r band (tf32)
    float* ps   = srs + 64*LDQ;     // overlay on srs rows 64..127
    float* posb = srs + 128*LDQ;    // 64*132
    float* rwbs = posb + 64*LDP;    // 64
    float* rrbs = rwbs + 64;        // 64
    float* samk = rrbs + 64;        // 64
    float* sttd = samk + 64;        // 128
    float* smM  = sttd + 128;       // 64
    float* smL  = smM + 64;         // 64
    float* sCor = smL + 64;         // 64
    float* mprt = sCor + 64;        // 128 [2][64]
    float* lprt = mprt + 128;       // 128

    int tid = threadIdx.x, w = tid >> 5, lane = tid & 31;
    int g = lane >> 2, t = lane & 3;
    int mt = w & 3, nh = w >> 2;
    int mtb = mt * 16;
    int i0 = blockIdx.x * 64, n = blockIdx.y, b = blockIdx.z;

    const float* qbase = &g_qh[(((size_t)b*Nc + n)*Sc + i0) * Hc];
    const float* kbase = &g_kh[(((size_t)b*Nc + n)*Sc) * Hc];
    const float* vbase = &g_vh[(((size_t)b*Nc + n)*Sc) * Hc];
    const float* rbase = &g_rh[(size_t)n * Rc * Hc];

    #pragma unroll
    for (int p = 0; p < 4; p++) {
        int idx = tid + p*256;
        int m = idx >> 4, h4 = (idx & 15) * 4;
        *(float4*)(sq + m*LDQ + h4) = *(const float4*)(qbase + m*Hc + h4);
    }
    if (tid < 64) {
        rwbs[tid] = rwb[n*Hc + tid] * SCALE;
        rrbs[tid] = rrb[n*Hc + tid] * SCALE;
        smM[tid] = -3.0e38f; smL[tid] = 0.f;
    }
    if (tid < 128) sttd[tid] = g_tt[(((size_t)b*Nc + n)*Sc + i0)*2 + tid];

    float4 of[4];
    #pragma unroll
    for (int nt = 0; nt < 4; nt++) of[nt] = make_float4(0.f,0.f,0.f,0.f);

    int u0 = mtb + g, u1 = u0 + 8;

    for (int j0 = 0; j0 < Sc; j0 += 64) {
        __syncthreads();
        // stage K (stride LDQ), band rs, amask
        #pragma unroll
        for (int p = 0; p < 4; p++) {
            int idx = tid + p*256;
            int j = idx >> 4, h4 = (idx & 15) * 4;
            *(float4*)(skv + j*LDQ + h4) =
                *(const float4*)(kbase + (size_t)(j0 + j)*Hc + h4);
        }
        int t_base = Sc - i0 - 63 + j0;
        #pragma unroll
        for (int p = 0; p < 8; p++) {
            int idx = tid + p*256;
            int r = idx >> 4, h4 = (idx & 15) * 4;
            int tt = t_base + r;
            float4 v = (tt >= 0 && tt < Rc)
                ? *(const float4*)(rbase + (size_t)tt*Hc + h4)
                : make_float4(0.f,0.f,0.f,0.f);
            *(float4*)(srs + r*LDQ + h4) = v;
        }
        if (tid < 64) samk[tid] = amask_g[b*Sc + j0 + tid];
        __syncthreads();

        // pos mma: pos_full[u][v] (64 x 128), two passes of 4 n-tiles
        #pragma unroll
        for (int half = 0; half < 2; half++) {
            float4 pf[4];
            #pragma unroll
            for (int nt = 0; nt < 4; nt++) pf[nt] = make_float4(0.f,0.f,0.f,0.f);
            #pragma unroll
            for (int ks = 0; ks < 8; ks++) {
                int kb = ks * 8;
                float bw0 = rrbs[kb+t], bw1 = rrbs[kb+t+4];
                unsigned a0 = f2tf(sq[u0*LDQ + kb+t  ] + bw0);
                unsigned a1 = f2tf(sq[u1*LDQ + kb+t  ] + bw0);
                unsigned a2 = f2tf(sq[u0*LDQ + kb+t+4] + bw1);
                unsigned a3 = f2tf(sq[u1*LDQ + kb+t+4] + bw1);
                #pragma unroll
                for (int nt = 0; nt < 4; nt++) {
                    int nb = nh*64 + half*32 + nt*8 + g;
                    unsigned b0 = __float_as_uint(srs[nb*LDQ + kb+t  ]);
                    unsigned b1 = __float_as_uint(srs[nb*LDQ + kb+t+4]);
                    mma8(pf[nt], a0,a1,a2,a3,b0,b1);
                }
            }
            #pragma unroll
            for (int nt = 0; nt < 4; nt++) {
                int v = nh*64 + half*32 + nt*8 + 2*t;
                *(float2*)(posb + u0*LDP + v) = make_float2(pf[nt].x, pf[nt].y);
                *(float2*)(posb + u1*LDP + v) = make_float2(pf[nt].z, pf[nt].w);
            }
        }
        // content mma: S (64 x 64)
        float4 sc[4];
        #pragma unroll
        for (int nt = 0; nt < 4; nt++) sc[nt] = make_float4(0.f,0.f,0.f,0.f);
        #pragma unroll
        for (int ks = 0; ks < 8; ks++) {
            int kb = ks * 8;
            float bw0 = rwbs[kb+t], bw1 = rwbs[kb+t+4];
            unsigned a0 = f2tf(sq[u0*LDQ + kb+t  ] + bw0);
            unsigned a1 = f2tf(sq[u1*LDQ + kb+t  ] + bw0);
            unsigned a2 = f2tf(sq[u0*LDQ + kb+t+4] + bw1);
            unsigned a3 = f2tf(sq[u1*LDQ + kb+t+4] + bw1);
            #pragma unroll
            for (int nt = 0; nt < 4; nt++) {
                int nb = nh*32 + nt*8 + g;
                unsigned b0 = __float_as_uint(skv[nb*LDQ + kb+t  ]);
                unsigned b1 = __float_as_uint(skv[nb*LDQ + kb+t+4]);
                mma8(sc[nt], a0,a1,a2,a3,b0,b1);
            }
        }
        __syncthreads();   // posb visible; skv(K) free

        // stage V (stride LDV)
        #pragma unroll
        for (int p = 0; p < 4; p++) {
            int idx = tid + p*256;
            int j = idx >> 4, h4 = (idx & 15) * 4;
            *(float4*)(skv + j*LDV + h4) =
                *(const float4*)(vbase + (size_t)(j0 + j)*Hc + h4);
        }
        // softmax part 1: full scores + partial row max
        int ii0 = i0 + u0, ii1 = i0 + u1;
        float td0 = sttd[2*u0], ts0 = sttd[2*u0+1];
        float td1 = sttd[2*u1], ts1 = sttd[2*u1+1];
        float mrow0 = -3.0e38f, mrow1 = -3.0e38f;
        #pragma unroll
        for (int nt = 0; nt < 4; nt++) {
            int j = nh*32 + nt*8 + 2*t, jj = j0 + j;
            float msk0 = INFV * (1.f - samk[j]);
            float msk1 = INFV * (1.f - samk[j+1]);
            float2 cls0 = *(const float2*)(clsm + (size_t)ii0*Sc + jj);
            float2 cls1 = *(const float2*)(clsm + (size_t)ii1*Sc + jj);
            unsigned short tz0 = *(const unsigned short*)(ttm + ((size_t)b*Sc+ii0)*Sc + jj);
            unsigned short tz1 = *(const unsigned short*)(ttm + ((size_t)b*Sc+ii1)*Sc + jj);
            float p00 = posb[u0*LDP + j   - u0 + 63];
            float p01 = posb[u0*LDP + j+1 - u0 + 63];
            float p10 = posb[u1*LDP + j   - u1 + 63];
            float p11 = posb[u1*LDP + j+1 - u1 + 63];
            sc[nt].x += cls0.x * (p00 + ((tz0 & 0xFF) ? ts0 : td0)); sc[nt].x -= msk0;
            sc[nt].y += cls0.y * (p01 + ((tz0 >> 8 ) ? ts0 : td0)); sc[nt].y -= msk1;
            sc[nt].z += cls1.x * (p10 + ((tz1 & 0xFF) ? ts1 : td1)); sc[nt].z -= msk0;
            sc[nt].w += cls1.y * (p11 + ((tz1 >> 8 ) ? ts1 : td1)); sc[nt].w -= msk1;
            mrow0 = fmaxf(mrow0, fmaxf(sc[nt].x, sc[nt].y));
            mrow1 = fmaxf(mrow1, fmaxf(sc[nt].z, sc[nt].w));
        }
        mrow0 = fmaxf(mrow0, __shfl_xor_sync(~0u, mrow0, 1));
        mrow0 = fmaxf(mrow0, __shfl_xor_sync(~0u, mrow0, 2));
        mrow1 = fmaxf(mrow1, __shfl_xor_sync(~0u, mrow1, 1));
        mrow1 = fmaxf(mrow1, __shfl_xor_sync(~0u, mrow1, 2));
        if (t == 0) { mprt[nh*64 + u0] = mrow0; mprt[nh*64 + u1] = mrow1; }
        __syncthreads();

        // softmax part 2: exp, P staging, partial sums
        float mn0 = fmaxf(smM[u0], fmaxf(mprt[u0], mprt[64 + u0]));
        float mn1 = fmaxf(smM[u1], fmaxf(mprt[u1], mprt[64 + u1]));
        float ls0 = 0.f, ls1 = 0.f;
        #pragma unroll
        for (int nt = 0; nt < 4; nt++) {
            int j = nh*32 + nt*8 + 2*t;
            float e00 = __expf(sc[nt].x - mn0), e01 = __expf(sc[nt].y - mn0);
            float e10 = __expf(sc[nt].z - mn1), e11 = __expf(sc[nt].w - mn1);
            ls0 += e00 + e01; ls1 += e10 + e11;
            *(float2*)(ps + u0*LDQ + j) =
                make_float2(__uint_as_float(f2tf(e00)), __uint_as_float(f2tf(e01)));
            *(float2*)(ps + u1*LDQ + j) =
                make_float2(__uint_as_float(f2tf(e10)), __uint_as_float(f2tf(e11)));
        }
        ls0 += __shfl_xor_sync(~0u, ls0, 1); ls0 += __shfl_xor_sync(~0u, ls0, 2);
        ls1 += __shfl_xor_sync(~0u, ls1, 1); ls1 += __shfl_xor_sync(~0u, ls1, 2);
        if (t == 0) { lprt[nh*64 + u0] = ls0; lprt[nh*64 + u1] = ls1; }
        __syncthreads();

        if (tid < 64) {
            int u = tid;
            float mn = fmaxf(smM[u], fmaxf(mprt[u], mprt[64 + u]));
            float corr = __expf(smM[u] - mn);
            smL[u] = smL[u] * corr + lprt[u] + lprt[64 + u];
            smM[u] = mn; sCor[u] = corr;
        }
        __syncthreads();

        // PV mma: O += P @ V  (warp tile 16 x 32 over (i, h))
        float cr0 = sCor[u0], cr1 = sCor[u1];
        #pragma unroll
        for (int nt = 0; nt < 4; nt++) {
            of[nt].x *= cr0; of[nt].y *= cr0;
            of[nt].z *= cr1; of[nt].w *= cr1;
        }
        #pragma unroll
        for (int ks = 0; ks < 8; ks++) {
            int kb = ks * 8;
            unsigned a0 = __float_as_uint(ps[u0*LDQ + kb+t  ]);
            unsigned a1 = __float_as_uint(ps[u1*LDQ + kb+t  ]);
            unsigned a2 = __float_as_uint(ps[u0*LDQ + kb+t+4]);
            unsigned a3 = __float_as_uint(ps[u1*LDQ + kb+t+4]);
            #pragma unroll
            for (int nt = 0; nt < 4; nt++) {
                int nb = nh*32 + nt*8 + g;
                unsigned b0 = __float_as_uint(skv[(kb+t  )*LDV + nb]);
                unsigned b1 = __float_as_uint(skv[(kb+t+4)*LDV + nb]);
                mma8(of[nt], a0,a1,a2,a3,b0,b1);
            }
        }
    }

    float inv0 = 1.f / smL[u0], inv1 = 1.f / smL[u1];
    float* outb = &g_av[(((size_t)b*Nc + n)*Sc + i0) * Hc];
    #pragma unroll
    for (int nt = 0; nt < 4; nt++) {
        int h = nh*32 + nt*8 + 2*t;
        *(float2*)(outb + (size_t)u0*Hc + h) =
            make_float2(__uint_as_float(f2tf(of[nt].x * inv0)),
                        __uint_as_float(f2tf(of[nt].y * inv0)));
        *(float2*)(outb + (size_t)u1*Hc + h) =
            make_float2(__uint_as_float(f2tf(of[nt].z * inv1)),
                        __uint_as_float(f2tf(of[nt].w * inv1)));
    }
}

// ---------------- LayerNorm ----------------
__global__ __launch_bounds__(256)
void ln_kernel(const float* __restrict__ lng, const float* __restrict__ lnb,
               float* __restrict__ out) {
    __shared__ float red[8];
    __shared__ float stat;
    int row = blockIdx.x;
    const float* x = &g_x[(size_t)row * Dc];
    int t = threadIdx.x;
    float v[3];
    float s = 0.f;
    #pragma unroll
    for (int p = 0; p < 3; p++) { v[p] = x[t + p*256]; s += v[p]; }
    #pragma unroll
    for (int off = 16; off; off >>= 1) s += __shfl_xor_sync(~0u, s, off);
    if ((t & 31) == 0) red[t >> 5] = s;
    __syncthreads();
    if (t < 32) {
        float r = (t < 8) ? red[t] : 0.f;
        #pragma unroll
        for (int off = 4; off; off >>= 1) r += __shfl_xor_sync(~0u, r, off);
        if (t == 0) stat = r * (1.f / Dc);
    }
    __syncthreads();
    float mu = stat;
    float s2 = 0.f;
    #pragma unroll
    for (int p = 0; p < 3; p++) { float d = v[p] - mu; s2 += d*d; }
    #pragma unroll
    for (int off = 16; off; off >>= 1) s2 += __shfl_xor_sync(~0u, s2, off);
    if ((t & 31) == 0) red[t >> 5] = s2;
    __syncthreads();
    if (t < 32) {
        float r = (t < 8) ? red[t] : 0.f;
        #pragma unroll
        for (int off = 4; off; off >>= 1) r += __shfl_xor_sync(~0u, r, off);
        if (t == 0) stat = rsqrtf(r * (1.f / Dc) + EPSV);
    }
    __syncthreads();
    float rstd = stat;
    #pragma unroll
    for (int p = 0; p < 3; p++) {
        int i = t + p*256;
        out[(size_t)row*Dc + i] = (v[p] - mu) * rstd * lng[i] + lnb[i];
    }
}

// ---------------- launch ----------------
extern "C" void kernel_launch(void* const* d_in, const int* in_sizes, int n_in,
                              void* d_out, int out_size) {
    const float* query = (const float*)d_in[0];
    const float* key   = (const float*)d_in[1];
    const float* value = (const float*)d_in[2];
    const float* pose  = (const float*)d_in[3];
    const unsigned char* ttm = (const unsigned char*)d_in[4];
    const float* amask = (const float*)d_in[5];
    const float* clsm  = (const float*)d_in[6];
    const float* Wq    = (const float*)d_in[7];
    const float* Wk    = (const float*)d_in[8];
    const float* bk    = (const float*)d_in[9];
    const float* Wv    = (const float*)d_in[10];
    const float* bv    = (const float*)d_in[11];
    const float* rwb   = (const float*)d_in[12];
    const float* rrb   = (const float*)d_in[13];
    const float* rker  = (const float*)d_in[14];
    const float* rsb   = (const float*)d_in[15];
    const float* seg   = (const float*)d_in[16];
    const float* Wo    = (const float*)d_in[17];
    const float* bo    = (const float*)d_in[18];
    const float* lng   = (const float*)d_in[19];
    const float* lnb   = (const float*)d_in[20];
    float* out = (float*)d_out;

    float *qh, *kh, *vh, *rh;
    cudaGetSymbolAddress((void**)&qh, g_qh);
    cudaGetSymbolAddress((void**)&kh, g_kh);
    cudaGetSymbolAddress((void**)&vh, g_vh);
    cudaGetSymbolAddress((void**)&rh, g_rh);

    dim3 blk(256);
    gemm_proj_t<<<dim3(12, 32), blk>>>(query, Wq, nullptr, SCALE, 10, qh);
    gemm_proj_t<<<dim3(12, 32), blk>>>(key,   Wk, bk,      1.0f, 10, kh);
    gemm_proj_t<<<dim3(12, 32), blk>>>(value, Wv, bv,      1.0f, 10, vh);
    gemm_proj_t<<<dim3(12, 16), blk>>>(pose,  rker, nullptr, 1.0f, 11, rh);

    tt_kernel<<<Bc*Nc*Sc/8, blk>>>(rsb, seg);

    size_t smem = (size_t)(64*LDQ + 64*LDV + 128*LDQ + 64*LDP + 768) * sizeof(float);
    cudaFuncSetAttribute(attn_kernel, cudaFuncAttributeMaxDynamicSharedMemorySize,
                         (int)smem);
    attn_kernel<<<dim3(Sc/64, Nc, Bc), blk, smem>>>(rwb, rrb, ttm, amask, clsm);

    gemm_out_t<<<dim3(12, 32), blk>>>(Wo, bo, query);

    ln_kernel<<<Bc*Sc, blk>>>(lng, lnb, out);
}